// round 16
// baseline (speedup 1.0000x reference)
#include <cuda_runtime.h>

#define NQ 1024
#define NK 2048
#define D  64
typedef unsigned long long ull;

__device__ float g_qp [NQ * D];
__device__ float g_kpb[NK * D];
__device__ float g_vt [NK * D];
__device__ float g_sep[NQ * 32];
__device__ unsigned g_launch;
__device__ unsigned g_fqc[16], g_fkc[32];
__device__ unsigned g_row[16], g_zf;

__device__ __forceinline__ unsigned ldacq(const unsigned* p) {
    unsigned v; asm volatile("ld.acquire.gpu.global.u32 %0, [%1];" : "=r"(v) : "l"(p)); return v;
}
__device__ __forceinline__ void relinc(unsigned* p) {
    asm volatile("red.release.gpu.global.add.u32 [%0], 1;" :: "l"(p));
}
__device__ __forceinline__ unsigned su32(const void* p) {
    return (unsigned)__cvta_generic_to_shared(p);
}
#define CPA16(dst, src) asm volatile("cp.async.ca.shared.global [%0], [%1], 16;" :: "r"(dst), "l"(src))
#define CPCOMMIT() asm volatile("cp.async.commit_group;")
#define CPWAIT() asm volatile("cp.async.wait_group 0;")
#define FMA2(acc, a, b) asm("fma.rn.f32x2 %0, %1, %2, %0;" : "+l"(acc) : "l"(a), "l"(b))
#define RELU_FMA2(acc, a, b, w) asm("{\n\t.reg .b64 t;\n\t.reg .f32 lo, hi;\n\t" \
    "add.rn.f32x2 t, %1, %2;\n\tmov.b64 {lo, hi}, t;\n\t"                        \
    "max.f32 lo, lo, 0f00000000;\n\tmax.f32 hi, hi, 0f00000000;\n\t"             \
    "mov.b64 t, {lo, hi};\n\tfma.rn.f32x2 %0, %3, t, %0;\n\t}"                   \
    : "+l"(acc) : "l"(a), "l"(b), "l"(w))

// One kernel, grid (16,32) = 512 blocks @ 3 CTA/SM.
// Phase 0 (lin<192: proj producer; lin 192..319: transpose, tv<16 zero out).
// Phase 1: scores tile 64q x 64k + sep partial + row flag.
// Phase 2 (lin<256): pv unit q16 x ksplit4, flag-synchronized.
__global__ void __launch_bounds__(256, 3)
k_fused(const float* __restrict__ query, const float* __restrict__ key,
        const float* __restrict__ value, const float* __restrict__ W1,
        const float* __restrict__ b1, const float* __restrict__ W2,
        const float* __restrict__ b2, float* out,
        float* __restrict__ scores)
{
    __shared__ __align__(16) float pool[11264];   // 45056 B, phase-aliased
    __shared__ unsigned s_call;

    int tid = threadIdx.x;
    int qt = blockIdx.x, kt = blockIdx.y;
    int lin = kt * 16 + qt;

    if (tid == 0) {
        unsigned my; asm volatile("atom.relaxed.gpu.global.add.u32 %0, [%1], 1;" : "=r"(my) : "l"(&g_launch));
        s_call = my / 512;
    }
    __syncthreads();
    unsigned call = s_call;

    float (*qs)[66] = (float (*)[66])pool;            // 16896 B
    float (*ks)[66] = (float (*)[66])(pool + 4224);   // 16896 B
    ull* w2s = (ull*)(pool + 8448);                   // 256 B

    // ---------------- Phase 0: producers ----------------
    if (lin < 192) {
        float (*Ws)[66] = (float (*)[66])qs;
        float (*Xs)[16] = (float (*)[16])ks;
        bool isQ = (lin < 64);
        int c0 = (isQ ? lin : (lin - 64)) * 16;
        const float* src = isQ ? query : key;
        int stride = isQ ? NQ : NK;
        int wofs = isQ ? 0 : D;
        {
            int h = tid >> 2, ds = (tid & 3) * 16;
            const float* wr = W1 + h * (2 * D) + wofs + ds;
            #pragma unroll
            for (int j = 0; j < 4; j++) {
                float4 v = *(const float4*)(wr + 4 * j);
                Ws[ds + 4*j + 0][h] = v.x; Ws[ds + 4*j + 1][h] = v.y;
                Ws[ds + 4*j + 2][h] = v.z; Ws[ds + 4*j + 3][h] = v.w;
            }
        }
        {
            int d = tid >> 2, c = (tid & 3) * 4;
            *(float4*)&Xs[d][c] = *(const float4*)&src[d * stride + c0 + c];
        }
        __syncthreads();
        int h = tid & 63, cg = tid >> 6;
        float bias = isQ ? 0.0f : b1[h];
        float a0 = bias, a1 = bias, a2 = bias, a3 = bias;
        #pragma unroll 16
        for (int d = 0; d < D; d++) {
            float w = Ws[d][h];
            float4 x = *(float4*)&Xs[d][cg * 4];
            a0 += w * x.x; a1 += w * x.y; a2 += w * x.z; a3 += w * x.w;
        }
        float* dst = (isQ ? g_qp : g_kpb) + (c0 + cg * 4) * D + h;
        dst[0] = a0; dst[D] = a1; dst[2 * D] = a2; dst[3 * D] = a3;

        __threadfence();
        __syncthreads();
        if (tid == 0) relinc(isQ ? &g_fqc[lin >> 2] : &g_fkc[(lin - 64) >> 2]);
        __syncthreads();
    } else if (lin < 320) {
        float (*tile)[33] = (float (*)[33])pool;
        int tv = lin - 192;
        if (tv < 16) {
            #pragma unroll
            for (int j = 0; j < 4; j++)
                *(float4*)&out[tv * 4096 + j * 1024 + tid * 4] = make_float4(0.f,0.f,0.f,0.f);
            __threadfence();
            __syncthreads();
            if (tid == 0) relinc(&g_zf);
        }
        int k0 = (tv >> 1) * 32, d0 = (tv & 1) * 32;
        int tx2 = tid & 31, ty2 = tid >> 5;
        #pragma unroll
        for (int r = 0; r < 32; r += 8)
            tile[ty2 + r][tx2] = value[(d0 + ty2 + r) * NK + k0 + tx2];
        __syncthreads();
        #pragma unroll
        for (int r = 0; r < 32; r += 8)
            g_vt[(k0 + ty2 + r) * D + d0 + tx2] = tile[tx2][ty2 + r];
        __syncthreads();
    }

    // ---------------- Phase 1: scores tile ----------------
    if (tid == 0) {
        unsigned tgt = 4 * (call + 1);
        while (ldacq(&g_fqc[qt]) < tgt) __nanosleep(32);
        while (ldacq(&g_fkc[kt]) < tgt) __nanosleep(32);
    }
    __syncthreads();

    int qbase = qt * 64, kbase = kt * 64;
    for (int i = tid; i < 64 * 32; i += 256) {
        int r = i >> 5, c = (i & 31) * 2;
        *(float2*)&qs[r][c] = *(const float2*)&g_qp [(qbase + r) * D + c];
        *(float2*)&ks[r][c] = *(const float2*)&g_kpb[(kbase + r) * D + c];
    }
    if (tid < 32) {
        float2 w = *(const float2*)&W2[2 * tid];
        ull p; asm("mov.b64 %0, {%1,%2};" : "=l"(p) : "f"(w.x), "f"(w.y));
        w2s[tid] = p;
    }
    __syncthreads();

    {
        int tx = tid & 15, ty = tid >> 4;
        ull acc[4][4];
        #pragma unroll
        for (int i = 0; i < 4; i++)
            #pragma unroll
            for (int j = 0; j < 4; j++) acc[i][j] = 0ull;

        #pragma unroll 4
        for (int h = 0; h < 64; h += 2) {
            ull w2 = w2s[h >> 1];
            ull a[4], bb[4];
            #pragma unroll
            for (int i = 0; i < 4; i++) a[i]  = *(ull*)&qs[ty + 16 * i][h];
            #pragma unroll
            for (int j = 0; j < 4; j++) bb[j] = *(ull*)&ks[tx + 16 * j][h];
            #pragma unroll
            for (int i = 0; i < 4; i++)
                #pragma unroll
                for (int j = 0; j < 4; j++)
                    RELU_FMA2(acc[i][j], a[i], bb[j], w2);
        }

        float bias = b2[0];
        #pragma unroll
        for (int i = 0; i < 4; i++) {
            int q = qbase + ty + 16 * i;
            float rsum = 0.0f;
            #pragma unroll
            for (int j = 0; j < 4; j++) {
                float lo, hi;
                asm("mov.b64 {%0,%1}, %2;" : "=f"(lo), "=f"(hi) : "l"(acc[i][j]));
                float s = lo + hi + bias;
                scores[q * NK + kbase + tx + 16 * j] = s;
                rsum += __expf(s);
            }
            #pragma unroll
            for (int o = 8; o > 0; o >>= 1)
                rsum += __shfl_xor_sync(~0u, rsum, o);
            if (tx == 0) g_sep[q * 32 + kt] = rsum;
        }
    }

    __threadfence();
    __syncthreads();
    if (tid == 0) relinc(&g_row[qt]);

    // ---------------- Phase 2: pv unit (blocks lin < 256) ----------------
    if (lin >= 256) return;
    __syncthreads();                      // safe to alias pool

    float (*vs)[64][68] = (float (*)[64][68])pool;        // 34816 B
    float (*ps)[64][20] = (float (*)[64][20])(pool + 8704); // 10240 B

    int q0 = (lin >> 2) * 16;
    int kb0 = (lin & 3) * (NK / 4);
    int w = tid >> 5, lane = tid & 31;
    int ksl = w & 3, dhalf = w >> 2;
    int myd = dhalf * 32 + lane;

    // stage V tile 0 before spinning (independent of scores)
    int vk = tid >> 2, vh = (tid & 3) * 16;
    {
        const float* src = g_vt + (kb0 + vk) * D + vh;
        unsigned dst = su32(&vs[0][vk][vh]);
        #pragma unroll
        for (int j = 0; j < 4; j++) CPA16(dst + 16 * j, src + 4 * j);
        CPCOMMIT();
    }

    if (tid == 0) {
        unsigned t1 = 16 * (call + 1);
        while (ldacq(&g_zf) < t1) __nanosleep(32);
        unsigned t2 = 32 * (call + 1);
        while (ldacq(&g_row[q0 >> 6]) < t2) __nanosleep(32);
    }
    __syncthreads();

    int skk = tid & 15, sq = tid >> 4;
    float se = 0.0f;
    {
        const float* sep = g_sep + (q0 + sq) * 32;
        #pragma unroll
        for (int j = 0; j < 32; j += 4) {
            float4 v = *(const float4*)(sep + j);
            se += (v.x + v.y) + (v.z + v.w);
        }
    }
    float ri = 1.0f / se;
    const float* srow = scores + (q0 + sq) * NK + kb0 + skk;

    float sc[4];
    #pragma unroll
    for (int i = 0; i < 4; i++) sc[i] = srow[16 * i];

    ull acc[8] = {0,0,0,0,0,0,0,0};

    for (int t = 0; t < 8; t++) {
        int buf = t & 1;
        CPWAIT();
        __syncthreads();
        #pragma unroll
        for (int i = 0; i < 4; i++)
            ps[buf][skk + 16 * i][sq] = __expf(sc[i]) * ri;
        if (t < 7) {
            const float* src = g_vt + (kb0 + (t + 1) * 64 + vk) * D + vh;
            unsigned dst = su32(&vs[buf ^ 1][vk][vh]);
            #pragma unroll
            for (int j = 0; j < 4; j++) CPA16(dst + 16 * j, src + 4 * j);
            CPCOMMIT();
            #pragma unroll
            for (int i = 0; i < 4; i++) sc[i] = srow[(t + 1) * 64 + 16 * i];
        }
        __syncthreads();

        int kb = ksl * 16;
        #pragma unroll
        for (int u = 0; u < 16; u++) {
            int kk = kb + u;
            float v = vs[buf][kk][myd];
            ulonglong2 pA = *(ulonglong2*)&ps[buf][kk][0];
            ulonglong2 pB = *(ulonglong2*)&ps[buf][kk][4];
            ulonglong2 pC = *(ulonglong2*)&ps[buf][kk][8];
            ulonglong2 pD = *(ulonglong2*)&ps[buf][kk][12];
            ull vx;
            asm("mov.b64 %0, {%1,%1};" : "=l"(vx) : "f"(v));
            FMA2(acc[0], pA.x, vx); FMA2(acc[1], pA.y, vx);
            FMA2(acc[2], pB.x, vx); FMA2(acc[3], pB.y, vx);
            FMA2(acc[4], pC.x, vx); FMA2(acc[5], pC.y, vx);
            FMA2(acc[6], pD.x, vx); FMA2(acc[7], pD.y, vx);
        }
    }

    __syncthreads();
    float* red = (float*)pool;
    int base = (w * 32 + lane) * 16;
    #pragma unroll
    for (int jp = 0; jp < 8; jp++) {
        float lo, hi;
        asm("mov.b64 {%0,%1}, %2;" : "=f"(lo), "=f"(hi) : "l"(acc[jp]));
        red[base + 2 * jp] = lo; red[base + 2 * jp + 1] = hi;
    }
    __syncthreads();

    #pragma unroll
    for (int r = tid; r < 1024; r += 256) {
        int d = r >> 4, q = r & 15;
        int dh = d >> 5, ln = d & 31;
        float s = 0.0f;
        #pragma unroll
        for (int ksx = 0; ksx < 4; ksx++)
            s += red[((dh * 4 + ksx) * 32 + ln) * 16 + q];
        atomicAdd(&out[d * NQ + q0 + q], s);
    }
}

// ---------------------------------------------------------------------------
extern "C" void kernel_launch(void* const* d_in, const int* in_sizes, int n_in,
                              void* d_out, int out_size)
{
    const float* query = (const float*)d_in[0];
    const float* key   = (const float*)d_in[1];
    const float* value = (const float*)d_in[2];
    const float* W1    = (const float*)d_in[3];
    const float* b1    = (const float*)d_in[4];
    const float* W2    = (const float*)d_in[5];
    const float* b2    = (const float*)d_in[6];

    float* out_p    = (float*)d_out;
    float* scores_p = (float*)d_out + NQ * D;

    k_fused<<<dim3(16, 32), 256>>>(query, key, value, W1, b1, W2, b2, out_p, scores_p);
}

// round 17
// speedup vs baseline: 1.2243x; 1.2243x over previous
#include <cuda_runtime.h>

#define NQ 1024
#define NK 2048
#define D  64
typedef unsigned long long ull;

__device__ float g_qp [NQ * D];
__device__ float g_kpb[NK * D];
__device__ float g_vt [NK * D];
__device__ float g_sep[NQ * 32];
__device__ unsigned g_launch;
__device__ unsigned g_fqc[16], g_fkc[32], g_fvt[32], g_zf;

__device__ __forceinline__ unsigned ldacq(const unsigned* p) {
    unsigned v; asm volatile("ld.acquire.gpu.global.u32 %0, [%1];" : "=r"(v) : "l"(p)); return v;
}
__device__ __forceinline__ void relinc(unsigned* p) {
    asm volatile("red.release.gpu.global.add.u32 [%0], 1;" :: "l"(p));
}
__device__ __forceinline__ unsigned su32(const void* p) {
    return (unsigned)__cvta_generic_to_shared(p);
}
#define CPA16(dst, src) asm volatile("cp.async.ca.shared.global [%0], [%1], 16;" :: "r"(dst), "l"(src))
#define CPCOMMIT() asm volatile("cp.async.commit_group;")
#define CPWAIT() asm volatile("cp.async.wait_group 0;")
#define FMA2(acc, a, b) asm("fma.rn.f32x2 %0, %1, %2, %0;" : "+l"(acc) : "l"(a), "l"(b))
#define RELU_FMA2(acc, a, b, w) asm("{\n\t.reg .b64 t;\n\t.reg .f32 lo, hi;\n\t" \
    "add.rn.f32x2 t, %1, %2;\n\tmov.b64 {lo, hi}, t;\n\t"                        \
    "max.f32 lo, lo, 0f00000000;\n\tmax.f32 hi, hi, 0f00000000;\n\t"             \
    "mov.b64 t, {lo, hi};\n\tfma.rn.f32x2 %0, %3, t, %0;\n\t}"                   \
    : "+l"(acc) : "l"(a), "l"(b), "l"(w))

// Kernel A: grid (16,32)=512 blocks @ 3 CTA/SM.
// Phase 0: lin<192 proj producers; lin 192..319 V-transpose (tv<16 also zero out).
// Phase 1: scores tile 64q x 64k + exps + sep partials.
// Phase 2: numerator GEMM (exp tile x V tile), 4 passes of 16 q, atomicAdd to out.
__global__ void __launch_bounds__(256, 3)
k_scores(const float* __restrict__ query, const float* __restrict__ key,
         const float* __restrict__ value, const float* __restrict__ W1,
         const float* __restrict__ b1, const float* __restrict__ W2,
         const float* __restrict__ b2, float* out,
         float* __restrict__ scores)
{
    __shared__ __align__(16) float pool[11264];    // 45056 B
    __shared__ unsigned s_call;

    int tid = threadIdx.x;
    int qt = blockIdx.x, kt = blockIdx.y;
    int lin = kt * 16 + qt;

    if (tid == 0) {
        unsigned my; asm volatile("atom.relaxed.gpu.global.add.u32 %0, [%1], 1;" : "=r"(my) : "l"(&g_launch));
        s_call = my / 512;
    }
    __syncthreads();
    unsigned call = s_call;

    float (*qs)[66] = (float (*)[66])pool;           // 16896 B
    float (*ks)[66] = (float (*)[66])(pool + 4224);  // 16896 B
    ull* w2s = (ull*)(pool + 8448);                  // 256 B

    // ---------------- Phase 0: producers ----------------
    if (lin < 192) {
        float (*Ws)[66] = (float (*)[66])qs;
        float (*Xs)[16] = (float (*)[16])ks;
        bool isQ = (lin < 64);
        int c0 = (isQ ? lin : (lin - 64)) * 16;
        const float* src = isQ ? query : key;
        int stride = isQ ? NQ : NK;
        int wofs = isQ ? 0 : D;
        {
            int h = tid >> 2, ds = (tid & 3) * 16;
            const float* wr = W1 + h * (2 * D) + wofs + ds;
            #pragma unroll
            for (int j = 0; j < 4; j++) {
                float4 v = *(const float4*)(wr + 4 * j);
                Ws[ds + 4*j + 0][h] = v.x; Ws[ds + 4*j + 1][h] = v.y;
                Ws[ds + 4*j + 2][h] = v.z; Ws[ds + 4*j + 3][h] = v.w;
            }
        }
        {
            int d = tid >> 2, c = (tid & 3) * 4;
            *(float4*)&Xs[d][c] = *(const float4*)&src[d * stride + c0 + c];
        }
        __syncthreads();
        int h = tid & 63, cg = tid >> 6;
        float bias = isQ ? 0.0f : b1[h];
        float a0 = bias, a1 = bias, a2 = bias, a3 = bias;
        #pragma unroll 16
        for (int d = 0; d < D; d++) {
            float w = Ws[d][h];
            float4 x = *(float4*)&Xs[d][cg * 4];
            a0 += w * x.x; a1 += w * x.y; a2 += w * x.z; a3 += w * x.w;
        }
        float* dst = (isQ ? g_qp : g_kpb) + (c0 + cg * 4) * D + h;
        dst[0] = a0; dst[D] = a1; dst[2 * D] = a2; dst[3 * D] = a3;

        __threadfence();
        __syncthreads();
        if (tid == 0) relinc(isQ ? &g_fqc[lin >> 2] : &g_fkc[(lin - 64) >> 2]);
        __syncthreads();
    } else if (lin < 320) {
        float (*tile)[33] = (float (*)[33])pool;
        int tv = lin - 192;                       // 0..127
        if (tv < 16) {
            #pragma unroll
            for (int j = 0; j < 4; j++)
                *(float4*)&out[tv * 4096 + j * 1024 + tid * 4] = make_float4(0.f,0.f,0.f,0.f);
            __threadfence();
            __syncthreads();
            if (tid == 0) relinc(&g_zf);
        }
        int k0 = (tv >> 1) * 32, d0 = (tv & 1) * 32;
        int tx2 = tid & 31, ty2 = tid >> 5;
        #pragma unroll
        for (int r = 0; r < 32; r += 8)
            tile[ty2 + r][tx2] = value[(d0 + ty2 + r) * NK + k0 + tx2];
        __syncthreads();
        #pragma unroll
        for (int r = 0; r < 32; r += 8)
            g_vt[(k0 + ty2 + r) * D + d0 + tx2] = tile[tx2][ty2 + r];
        __threadfence();
        __syncthreads();
        if (tid == 0) relinc(&g_fvt[tv >> 2]);
        __syncthreads();
    }

    // ---------------- Wait for inputs ----------------
    if (tid == 0) {
        unsigned tgt = 4 * (call + 1);
        while (ldacq(&g_fqc[qt]) < tgt) __nanosleep(32);
        while (ldacq(&g_fkc[kt]) < tgt) __nanosleep(32);
        while (ldacq(&g_fvt[kt]) < tgt) __nanosleep(32);
        unsigned tz = 16 * (call + 1);
        while (ldacq(&g_zf) < tz) __nanosleep(32);
    }
    __syncthreads();

    // Prefetch V tile (hidden under scores compute). Lands in phase-2 region,
    // which overlaps ks: NOT safe — so stage into the tail region instead.
    float (*vs)[68] = (float (*)[68])pool;           // phase-2 alias (after compute)
    float (*ps)[20] = (float (*)[20])(pool + 4352);  // 1280 floats
    float* red = pool + 5632;                        // 4096 floats

    int qbase = qt * 64, kbase = kt * 64;
    for (int i = tid; i < 64 * 32; i += 256) {
        int r = i >> 5, c = (i & 31) * 2;
        *(float2*)&qs[r][c] = *(const float2*)&g_qp [(qbase + r) * D + c];
        *(float2*)&ks[r][c] = *(const float2*)&g_kpb[(kbase + r) * D + c];
    }
    if (tid < 32) {
        float2 w = *(const float2*)&W2[2 * tid];
        ull p; asm("mov.b64 %0, {%1,%2};" : "=l"(p) : "f"(w.x), "f"(w.y));
        w2s[tid] = p;
    }
    __syncthreads();

    int tx = tid & 15, ty = tid >> 4;
    float exps[4][4];
    {
        ull acc[4][4];
        #pragma unroll
        for (int i = 0; i < 4; i++)
            #pragma unroll
            for (int j = 0; j < 4; j++) acc[i][j] = 0ull;

        #pragma unroll 4
        for (int h = 0; h < 64; h += 2) {
            ull w2 = w2s[h >> 1];
            ull a[4], bb[4];
            #pragma unroll
            for (int i = 0; i < 4; i++) a[i]  = *(ull*)&qs[ty + 16 * i][h];
            #pragma unroll
            for (int j = 0; j < 4; j++) bb[j] = *(ull*)&ks[tx + 16 * j][h];
            #pragma unroll
            for (int i = 0; i < 4; i++)
                #pragma unroll
                for (int j = 0; j < 4; j++)
                    RELU_FMA2(acc[i][j], a[i], bb[j], w2);
        }

        float bias = b2[0];
        #pragma unroll
        for (int i = 0; i < 4; i++) {
            int q = qbase + ty + 16 * i;
            float rsum = 0.0f;
            #pragma unroll
            for (int j = 0; j < 4; j++) {
                float lo, hi;
                asm("mov.b64 {%0,%1}, %2;" : "=f"(lo), "=f"(hi) : "l"(acc[i][j]));
                float s = lo + hi + bias;
                scores[q * NK + kbase + tx + 16 * j] = s;
                float e = __expf(s);
                exps[i][j] = e;
                rsum += e;
            }
            #pragma unroll
            for (int o = 8; o > 0; o >>= 1)
                rsum += __shfl_xor_sync(~0u, rsum, o);
            if (tx == 0) g_sep[q * 32 + kt] = rsum;
        }
    }

    // ---------------- Phase 2: numerator GEMM ----------------
    __syncthreads();                       // qs/ks dead; pool re-purposed

    // load V tile [64 k][64 d] rows kt*64.. into vs (cp.async)
    {
        int vk = tid >> 2, vh = (tid & 3) * 16;
        const float* src = g_vt + (kbase + vk) * D + vh;
        unsigned dst = su32(&vs[vk][vh]);
        #pragma unroll
        for (int j = 0; j < 4; j++) CPA16(dst + 16 * j, src + 4 * j);
        CPCOMMIT();
        CPWAIT();
    }

    int w = tid >> 5, lane = tid & 31;
    int ksl = w & 3, dhalf = w >> 2;
    int myd = dhalf * 32 + lane;

    #pragma unroll
    for (int g = 0; g < 4; g++) {
        __syncthreads();                   // prior pass's ps reads done
        #pragma unroll
        for (int j = 0; j < 4; j++)
            ps[tx + 16 * j][ty] = exps[g][j];
        __syncthreads();

        ull acc[8] = {0,0,0,0,0,0,0,0};
        int kb = ksl * 16;
        #pragma unroll
        for (int u = 0; u < 16; u++) {
            int kk = kb + u;
            float v = vs[kk][myd];
            ulonglong2 pA = *(ulonglong2*)&ps[kk][0];
            ulonglong2 pB = *(ulonglong2*)&ps[kk][4];
            ulonglong2 pC = *(ulonglong2*)&ps[kk][8];
            ulonglong2 pD = *(ulonglong2*)&ps[kk][12];
            ull vx;
            asm("mov.b64 %0, {%1,%1};" : "=l"(vx) : "f"(v));
            FMA2(acc[0], pA.x, vx); FMA2(acc[1], pA.y, vx);
            FMA2(acc[2], pB.x, vx); FMA2(acc[3], pB.y, vx);
            FMA2(acc[4], pC.x, vx); FMA2(acc[5], pC.y, vx);
            FMA2(acc[6], pD.x, vx); FMA2(acc[7], pD.y, vx);
        }

        __syncthreads();                   // red region free (prior pass read)
        int base = (w * 32 + lane) * 16;
        #pragma unroll
        for (int jp = 0; jp < 8; jp++) {
            float lo, hi;
            asm("mov.b64 {%0,%1}, %2;" : "=f"(lo), "=f"(hi) : "l"(acc[jp]));
            red[base + 2 * jp] = lo; red[base + 2 * jp + 1] = hi;
        }
        __syncthreads();

        #pragma unroll
        for (int r = tid; r < 1024; r += 256) {
            int d = r >> 4, q = r & 15;
            int dh = d >> 5, ln = d & 31;
            float s = 0.0f;
            #pragma unroll
            for (int ksx = 0; ksx < 4; ksx++)
                s += red[((dh * 4 + ksx) * 32 + ln) * 16 + q];
            atomicAdd(&out[d * NQ + qbase + g * 16 + q], s);
        }
    }
}

// Kernel B: out[d][q] *= 1/Z[q]. 64 blocks x 256 thr.
__global__ void __launch_bounds__(256) k_scale(float* __restrict__ out)
{
    int tid = threadIdx.x;
    int q = blockIdx.x * 16 + (tid & 15);
    int dg = tid >> 4;                     // 16 groups x 4 d
    float se = 0.0f;
    const float* sep = g_sep + q * 32;
    #pragma unroll
    for (int j = 0; j < 32; j += 4) {
        float4 v = *(const float4*)(sep + j);
        se += (v.x + v.y) + (v.z + v.w);
    }
    float ri = 1.0f / se;
    #pragma unroll
    for (int i = 0; i < 4; i++) {
        int idx = (dg * 4 + i) * NQ + q;
        out[idx] *= ri;
    }
}

// ---------------------------------------------------------------------------
extern "C" void kernel_launch(void* const* d_in, const int* in_sizes, int n_in,
                              void* d_out, int out_size)
{
    const float* query = (const float*)d_in[0];
    const float* key   = (const float*)d_in[1];
    const float* value = (const float*)d_in[2];
    const float* W1    = (const float*)d_in[3];
    const float* b1    = (const float*)d_in[4];
    const float* W2    = (const float*)d_in[5];
    const float* b2    = (const float*)d_in[6];

    float* out_p    = (float*)d_out;
    float* scores_p = (float*)d_out + NQ * D;

    k_scores<<<dim3(16, 32), 256>>>(query, key, value, W1, b1, W2, b2, out_p, scores_p);
    k_scale<<<64, 256>>>(out_p);
}